// round 1
// baseline (speedup 1.0000x reference)
#include <cuda_runtime.h>

#define N_NODES 100000
#define N_EDGES 1600000
#define HID 128
#define GG 512
#define XSD 384                      // 3 * HID jumping-knowledge concat
#define NB ((N_NODES + 127) / 128)   // 782 gemm row-blocks
#define NV4 (N_NODES * 32)           // N*128/4 float4 count

// ---------------- scratch (static device globals; no allocation) ----------------
__device__ float g_y[N_NODES * HID];     // 51.2 MB  (pre-act linear output / relu'd input)
__device__ float g_agg[N_NODES * HID];   // 51.2 MB  (edge aggregation)
__device__ float g_xs[N_NODES * XSD];    // 153.6 MB (per-layer outputs, concatenated)
__device__ float g_pooled[GG * XSD];     // 768 KB
__device__ float g_sum[HID];
__device__ float g_sumsq[HID];
__device__ float g_scale[HID];
__device__ float g_shift[HID];
__device__ int   g_counts[GG];

// ---------------- helpers ----------------
__device__ __forceinline__ void red_add_v4(float* p, float4 v) {
    asm volatile("red.global.add.v4.f32 [%0], {%1, %2, %3, %4};"
                 :: "l"(p), "f"(v.x), "f"(v.y), "f"(v.z), "f"(v.w) : "memory");
}

// ---------------- zero kernels ----------------
__global__ void k_zero_agg_stats() {
    int idx = blockIdx.x * blockDim.x + threadIdx.x;
    if (idx < NV4) ((float4*)g_agg)[idx] = make_float4(0.f, 0.f, 0.f, 0.f);
    if (blockIdx.x == 0 && threadIdx.x < HID) {
        g_sum[threadIdx.x] = 0.f;
        g_sumsq[threadIdx.x] = 0.f;
    }
}

__global__ void k_zero_pool() {
    int idx = blockIdx.x * blockDim.x + threadIdx.x;
    if (idx < GG * XSD / 4) ((float4*)g_pooled)[idx] = make_float4(0.f, 0.f, 0.f, 0.f);
    if (idx < GG) g_counts[idx] = 0;
}

// ---------------- GEMM: C[M,128] = A[M,128] @ W[128,128] (row-major) ----------------
__global__ void __launch_bounds__(256, 2) k_gemm(
    const float* __restrict__ A, int lda,
    const float* __restrict__ W,
    float* __restrict__ C, int ldc)
{
    __shared__ float As[8][132];
    __shared__ float Bs[8][128];
    const int tid = threadIdx.x;
    const int tx = tid & 15, ty = tid >> 4;
    const int row0 = blockIdx.x * 128;

    const int arow = tid >> 1, acol = (tid & 1) * 4;
    const int brow = tid >> 5, bcol = (tid & 31) * 4;
    const int grow = row0 + arow;
    const bool avalid = grow < N_NODES;
    const float* Ap = A + (size_t)(avalid ? grow : 0) * lda + acol;
    const float* Wp = W + brow * 128 + bcol;

    float acc[8][8];
#pragma unroll
    for (int i = 0; i < 8; i++)
#pragma unroll
        for (int j = 0; j < 8; j++) acc[i][j] = 0.f;

    for (int k0 = 0; k0 < 128; k0 += 8) {
        float4 av = avalid ? *(const float4*)(Ap + k0) : make_float4(0.f, 0.f, 0.f, 0.f);
        float4 bv = *(const float4*)(Wp + k0 * 128);
        __syncthreads();
        As[acol + 0][arow] = av.x;
        As[acol + 1][arow] = av.y;
        As[acol + 2][arow] = av.z;
        As[acol + 3][arow] = av.w;
        *(float4*)&Bs[brow][bcol] = bv;
        __syncthreads();
#pragma unroll
        for (int k = 0; k < 8; k++) {
            float a[8], b[8];
            *(float4*)(a)     = *(const float4*)&As[k][ty * 8];
            *(float4*)(a + 4) = *(const float4*)&As[k][ty * 8 + 4];
            *(float4*)(b)     = *(const float4*)&Bs[k][tx * 8];
            *(float4*)(b + 4) = *(const float4*)&Bs[k][tx * 8 + 4];
#pragma unroll
            for (int i = 0; i < 8; i++)
#pragma unroll
                for (int j = 0; j < 8; j++) acc[i][j] += a[i] * b[j];
        }
    }
#pragma unroll
    for (int i = 0; i < 8; i++) {
        int r = row0 + ty * 8 + i;
        if (r < N_NODES) {
            float4* p = (float4*)(C + (size_t)r * ldc + tx * 8);
            p[0] = make_float4(acc[i][0], acc[i][1], acc[i][2], acc[i][3]);
            p[1] = make_float4(acc[i][4], acc[i][5], acc[i][6], acc[i][7]);
        }
    }
}

// ---------------- GEMM + bias + relu + BN-stat accumulation (writes xs slice) ----------------
__global__ void __launch_bounds__(256, 2) k_gemm_brs(
    const float* __restrict__ A, int lda,
    const float* __restrict__ W,
    const float* __restrict__ bias,
    float* __restrict__ C, int ldc)
{
    __shared__ float As[8][132];
    __shared__ float Bs[8][128];
    __shared__ float s_sum[128];
    __shared__ float s_sq[128];
    const int tid = threadIdx.x;
    const int tx = tid & 15, ty = tid >> 4;
    const int row0 = blockIdx.x * 128;

    const int arow = tid >> 1, acol = (tid & 1) * 4;
    const int brow = tid >> 5, bcol = (tid & 31) * 4;
    const int grow = row0 + arow;
    const bool avalid = grow < N_NODES;
    const float* Ap = A + (size_t)(avalid ? grow : 0) * lda + acol;
    const float* Wp = W + brow * 128 + bcol;

    if (tid < 128) { s_sum[tid] = 0.f; s_sq[tid] = 0.f; }

    float acc[8][8];
#pragma unroll
    for (int i = 0; i < 8; i++)
#pragma unroll
        for (int j = 0; j < 8; j++) acc[i][j] = 0.f;

    for (int k0 = 0; k0 < 128; k0 += 8) {
        float4 av = avalid ? *(const float4*)(Ap + k0) : make_float4(0.f, 0.f, 0.f, 0.f);
        float4 bv = *(const float4*)(Wp + k0 * 128);
        __syncthreads();
        As[acol + 0][arow] = av.x;
        As[acol + 1][arow] = av.y;
        As[acol + 2][arow] = av.z;
        As[acol + 3][arow] = av.w;
        *(float4*)&Bs[brow][bcol] = bv;
        __syncthreads();
#pragma unroll
        for (int k = 0; k < 8; k++) {
            float a[8], b[8];
            *(float4*)(a)     = *(const float4*)&As[k][ty * 8];
            *(float4*)(a + 4) = *(const float4*)&As[k][ty * 8 + 4];
            *(float4*)(b)     = *(const float4*)&Bs[k][tx * 8];
            *(float4*)(b + 4) = *(const float4*)&Bs[k][tx * 8 + 4];
#pragma unroll
            for (int i = 0; i < 8; i++)
#pragma unroll
                for (int j = 0; j < 8; j++) acc[i][j] += a[i] * b[j];
        }
    }

    float b2r[8];
    *(float4*)(b2r)     = *(const float4*)&bias[tx * 8];
    *(float4*)(b2r + 4) = *(const float4*)&bias[tx * 8 + 4];

    float ps[8], pq[8];
#pragma unroll
    for (int j = 0; j < 8; j++) { ps[j] = 0.f; pq[j] = 0.f; }

#pragma unroll
    for (int i = 0; i < 8; i++) {
        int r = row0 + ty * 8 + i;
        if (r < N_NODES) {
            float v[8];
#pragma unroll
            for (int j = 0; j < 8; j++) {
                v[j] = fmaxf(acc[i][j] + b2r[j], 0.f);
                ps[j] += v[j];
                pq[j] += v[j] * v[j];
            }
            float4* p = (float4*)(C + (size_t)r * ldc + tx * 8);
            p[0] = make_float4(v[0], v[1], v[2], v[3]);
            p[1] = make_float4(v[4], v[5], v[6], v[7]);
        }
    }
#pragma unroll
    for (int j = 0; j < 8; j++) {
        atomicAdd(&s_sum[tx * 8 + j], ps[j]);
        atomicAdd(&s_sq[tx * 8 + j], pq[j]);
    }
    __syncthreads();
    if (tid < 128) {
        atomicAdd(&g_sum[tid], s_sum[tid]);
        atomicAdd(&g_sumsq[tid], s_sq[tid]);
    }
}

// ---------------- layer-0 one-hot embedding add: y += W1[z] + W1[100+z] ----------------
__global__ void k_embed_add(const float* __restrict__ W1, const int* __restrict__ z) {
    int idx = blockIdx.x * blockDim.x + threadIdx.x;
    if (idx >= NV4) return;
    int i = idx >> 5;
    int c = (idx & 31) << 2;
    int zi = z[i];
    float4 w0 = *(const float4*)&W1[(size_t)zi * 128 + c];
    float4 w1 = *(const float4*)&W1[(size_t)(100 + zi) * 128 + c];
    float4 v = ((float4*)g_y)[idx];
    v.x += w0.x + w1.x; v.y += w0.y + w1.y;
    v.z += w0.z + w1.z; v.w += w0.w + w1.w;
    ((float4*)g_y)[idx] = v;
}

// ---------------- edge scatter: agg[dst] += y[src]  (warp per edge) ----------------
__global__ void k_scatter(const int* __restrict__ src, const int* __restrict__ dst) {
    int e = blockIdx.x * 8 + (threadIdx.x >> 5);
    if (e >= N_EDGES) return;
    int lane = threadIdx.x & 31;
    int s = src[e];
    int d = dst[e];
    float4 v = *(const float4*)&g_y[(size_t)s * 128 + lane * 4];
    red_add_v4(&g_agg[(size_t)d * 128 + lane * 4], v);
}

// ---------------- t = relu(y + agg + b1), in place into y ----------------
__global__ void k_relu_add(const float* __restrict__ b1) {
    int idx = blockIdx.x * blockDim.x + threadIdx.x;
    if (idx >= NV4) return;
    int c = (idx & 31) << 2;
    float4 y = ((float4*)g_y)[idx];
    float4 a = ((float4*)g_agg)[idx];
    float4 b = *(const float4*)&b1[c];
    y.x = fmaxf(y.x + a.x + b.x, 0.f);
    y.y = fmaxf(y.y + a.y + b.y, 0.f);
    y.z = fmaxf(y.z + a.z + b.z, 0.f);
    y.w = fmaxf(y.w + a.w + b.w, 0.f);
    ((float4*)g_y)[idx] = y;
}

// ---------------- BatchNorm finalize + apply ----------------
__global__ void k_bn_final(const float* __restrict__ gam, const float* __restrict__ bet) {
    int c = threadIdx.x;
    const float invN = 1.0f / (float)N_NODES;
    float mu = g_sum[c] * invN;
    float var = g_sumsq[c] * invN - mu * mu;
    float s = gam[c] * rsqrtf(fmaxf(var, 0.f) + 1e-5f);
    g_scale[c] = s;
    g_shift[c] = bet[c] - mu * s;
}

__global__ void k_bn_apply(int off4) {  // off4 = layer*32 (float4 units within 96-wide row)
    int idx = blockIdx.x * blockDim.x + threadIdx.x;
    if (idx >= NV4) return;
    int i = idx >> 5;
    int c4 = idx & 31;
    float4 sc = ((const float4*)g_scale)[c4];
    float4 sh = ((const float4*)g_shift)[c4];
    float4* p = (float4*)g_xs + (size_t)i * 96 + off4 + c4;
    float4 v = *p;
    v.x = v.x * sc.x + sh.x;
    v.y = v.y * sc.y + sh.y;
    v.z = v.z * sc.z + sh.z;
    v.w = v.w * sc.w + sh.w;
    *p = v;
}

// ---------------- pooling ----------------
__global__ void k_counts(const int* __restrict__ batch) {
    __shared__ int h[GG];
    for (int i = threadIdx.x; i < GG; i += blockDim.x) h[i] = 0;
    __syncthreads();
    for (int i = blockIdx.x * blockDim.x + threadIdx.x; i < N_NODES; i += gridDim.x * blockDim.x)
        atomicAdd(&h[batch[i]], 1);
    __syncthreads();
    for (int i = threadIdx.x; i < GG; i += blockDim.x)
        if (h[i]) atomicAdd(&g_counts[i], h[i]);
}

__global__ void k_pool(const int* __restrict__ batch) {
    int i = blockIdx.x * 8 + (threadIdx.x >> 5);
    if (i >= N_NODES) return;
    int lane = threadIdx.x & 31;
    int b = batch[i];
    const float4* xr = (const float4*)g_xs + (size_t)i * 96;
    float4* pr = (float4*)g_pooled + (size_t)b * 96;
#pragma unroll
    for (int j = 0; j < 3; j++) {
        float4 v = xr[lane + j * 32];
        red_add_v4((float*)(pr + lane + j * 32), v);
    }
}

// ---------------- final MLP: out[g] = relu(pooled/cnt @ Wl1 + bl1) @ Wl2 + bl2 ----------------
__global__ void __launch_bounds__(128) k_mlp(
    const float* __restrict__ Wl1, const float* __restrict__ bl1,
    const float* __restrict__ Wl2, const float* __restrict__ bl2,
    float* __restrict__ out)
{
    int g = blockIdx.x;
    int c = threadIdx.x;
    __shared__ float sp[XSD];
    __shared__ float red[128];
    float inv = 1.0f / fmaxf((float)g_counts[g], 1.0f);
    for (int k = c; k < XSD; k += 128) sp[k] = g_pooled[(size_t)g * XSD + k] * inv;
    __syncthreads();
    float acc = bl1[c];
    for (int k = 0; k < XSD; k++) acc += sp[k] * Wl1[(size_t)k * 128 + c];
    red[c] = fmaxf(acc, 0.f) * Wl2[c];
    __syncthreads();
    for (int s = 64; s > 0; s >>= 1) {
        if (c < s) red[c] += red[c + s];
        __syncthreads();
    }
    if (c == 0) out[g] = red[0] + bl2[0];
}

// ---------------- host ----------------
extern "C" void kernel_launch(void* const* d_in, const int* in_sizes, int n_in,
                              void* d_out, int out_size) {
    (void)in_sizes; (void)n_in; (void)out_size;
    const float* x     = (const float*)d_in[0];
    const int*   z     = (const int*)d_in[1];
    const int*   ei    = (const int*)d_in[2];
    const int*   batch = (const int*)d_in[3];
    const float *W1[3], *b1[3], *W2[3], *b2[3], *gam[3], *bet[3];
    for (int l = 0; l < 3; l++) {
        W1[l]  = (const float*)d_in[4 + 6 * l];
        b1[l]  = (const float*)d_in[5 + 6 * l];
        W2[l]  = (const float*)d_in[6 + 6 * l];
        b2[l]  = (const float*)d_in[7 + 6 * l];
        gam[l] = (const float*)d_in[8 + 6 * l];
        bet[l] = (const float*)d_in[9 + 6 * l];
    }
    const float* Wl1 = (const float*)d_in[22];
    const float* bl1 = (const float*)d_in[23];
    const float* Wl2 = (const float*)d_in[24];
    const float* bl2 = (const float*)d_in[25];
    const int* src = ei;
    const int* dst = ei + N_EDGES;

    void *yp = 0, *xsp = 0;
    cudaGetSymbolAddress(&yp, g_y);
    cudaGetSymbolAddress(&xsp, g_xs);
    float* yb  = (float*)yp;
    float* xsb = (float*)xsp;

    const int GR_EW = (NV4 + 255) / 256;          // 12500
    const int GR_E  = (N_EDGES + 7) / 8;          // 200000
    const int GR_P  = (N_NODES + 7) / 8;          // 12500

    for (int l = 0; l < 3; l++) {
        k_zero_agg_stats<<<GR_EW, 256>>>();
        if (l == 0) {
            // y = x @ W1_0[200:328]  then  y += W1_0[z] + W1_0[100+z]
            k_gemm<<<NB, 256>>>(x, 128, W1[0] + 200 * 128, yb, 128);
            k_embed_add<<<GR_EW, 256>>>(W1[0], z);
        } else {
            k_gemm<<<NB, 256>>>(xsb + (size_t)(l - 1) * 128, XSD, W1[l], yb, 128);
        }
        k_scatter<<<GR_E, 256>>>(src, dst);
        k_relu_add<<<GR_EW, 256>>>(b1[l]);
        k_gemm_brs<<<NB, 256>>>(yb, 128, W2[l], b2[l], xsb + (size_t)l * 128, XSD);
        k_bn_final<<<1, 128>>>(gam[l], bet[l]);
        k_bn_apply<<<GR_EW, 256>>>(l * 32);
    }

    k_zero_pool<<<192, 256>>>();
    k_counts<<<128, 256>>>(batch);
    k_pool<<<GR_P, 256>>>(batch);
    k_mlp<<<GG, 128>>>(Wl1, bl1, Wl2, bl2, (float*)d_out);
}

// round 3
// speedup vs baseline: 1.2549x; 1.2549x over previous
#include <cuda_runtime.h>
#include <cuda_bf16.h>
#include <cstdint>

#define N_NODES 100000
#define N_EDGES 1600000
#define HID 128
#define GG 512
#define XSD 384
#define NB 782                          // ceil(100000/128)
#define KP 136                          // smem pitch in bf16 elems
#define AIMG (128 * KP)                 // 17408 elems per tile image
#define SMEM_BYTES (4 * AIMG * 2)       // Ah, Al, Bh, Bl : 139264 B

// ---------------- scratch (static device globals; no allocation) ----------------
__device__ float g_y[N_NODES * HID];      // pre-aggregation features (gather source)
__device__ float g_agg[N_NODES * HID];    // self term + edge aggregation
__device__ float g_xs[N_NODES * XSD];     // per-layer raw (pre-BN-affine) outputs
__device__ uint4 g_wimg[6 * 4352];        // 6 weights x (hi+lo) bf16 images, [n][k] pitch KP
__device__ float g_pooled[GG * XSD];
__device__ float g_sum[3 * HID];
__device__ float g_sumsq[3 * HID];
__device__ float g_scale[3 * HID];
__device__ float g_shift[3 * HID];
__device__ int   g_counts[GG];

// ---------------- helpers ----------------
__device__ __forceinline__ void red_add_v4(float* p, float4 v) {
    asm volatile("red.global.add.v4.f32 [%0], {%1, %2, %3, %4};"
                 :: "l"(p), "f"(v.x), "f"(v.y), "f"(v.z), "f"(v.w) : "memory");
}

__device__ __forceinline__ void mma_bf16(float* c, uint32_t a0, uint32_t a1, uint32_t a2,
                                         uint32_t a3, uint32_t b0, uint32_t b1) {
    asm volatile(
        "mma.sync.aligned.m16n8k16.row.col.f32.bf16.bf16.f32 "
        "{%0,%1,%2,%3}, {%4,%5,%6,%7}, {%8,%9}, {%0,%1,%2,%3};"
        : "+f"(c[0]), "+f"(c[1]), "+f"(c[2]), "+f"(c[3])
        : "r"(a0), "r"(a1), "r"(a2), "r"(a3), "r"(b0), "r"(b1));
}

__device__ __forceinline__ uint32_t pack_bf2(__nv_bfloat16 lo, __nv_bfloat16 hi) {
    return (uint32_t)__bfloat16_as_ushort(lo) | ((uint32_t)__bfloat16_as_ushort(hi) << 16);
}

// ---------------- weight prep: W[k][n] -> transposed bf16 hi/lo images [n][k] ----------------
__global__ void k_prep(const float* __restrict__ w0, const float* __restrict__ w1,
                       const float* __restrict__ w2, const float* __restrict__ w3,
                       const float* __restrict__ w4, const float* __restrict__ w5) {
    int bb = blockIdx.x;
    if (bb < 6) {
        const float* W = bb == 0 ? w0 : bb == 1 ? w1 : bb == 2 ? w2 : bb == 3 ? w3 : bb == 4 ? w4 : w5;
        __nv_bfloat16* img = ((__nv_bfloat16*)g_wimg) + (size_t)bb * 2 * AIMG;
        for (int idx = threadIdx.x; idx < 16384; idx += 256) {
            int k = idx >> 7, n = idx & 127;
            float w = W[idx];
            __nv_bfloat16 h = __float2bfloat16(w);
            __nv_bfloat16 l = __float2bfloat16(w - __bfloat162float(h));
            img[n * KP + k] = h;
            img[AIMG + n * KP + k] = l;
        }
    } else {
        for (int i = threadIdx.x; i < 3 * HID; i += 256) { g_sum[i] = 0.f; g_sumsq[i] = 0.f; }
    }
}

// ---------------- fused bf16-emulated fp32 GEMM: D[M,128] = A[M,128] @ W[128,128] ----------------
// MODE 0: gemm1 layer0  : A = x,                   epi: v = D + W1[z] + W1[100+z]; write y, agg
// MODE 1: gemm1 layer>=1: A = xs_prev*scale+shift, epi: v = D;                     write y, agg
// MODE 2: gemm2         : A = relu(A + b1),        epi: v = relu(D + b2);          write xs slice
template <int MODE>
__global__ void __launch_bounds__(256, 1) k_mma(
    const float* __restrict__ A, int lda,
    const uint4* __restrict__ Wimg,
    const float* __restrict__ aux0,   // MODE1: scale  MODE2: b1
    const float* __restrict__ aux1,   // MODE1: shift
    const int* __restrict__ z,        // MODE0
    const float* __restrict__ Wfull,  // MODE0: full W1_0
    const float* __restrict__ b2,     // MODE2
    float* __restrict__ out0, int ld0,
    float* __restrict__ out1)
{
    extern __shared__ char smem[];
    __nv_bfloat16* sAh = (__nv_bfloat16*)smem;
    __nv_bfloat16* sAl = sAh + AIMG;
    __nv_bfloat16* sBh = sAl + AIMG;
    __nv_bfloat16* sBl = sBh + AIMG;
    const int tid = threadIdx.x;
    const int wid = tid >> 5, lane = tid & 31;
    const int row0 = blockIdx.x * 128;

    // ---- copy pre-swizzled B images (hi+lo = 4352 uint4) ----
    uint4* sB4 = (uint4*)sBh;
#pragma unroll
    for (int j = 0; j < 17; j++) sB4[tid + j * 256] = Wimg[tid + j * 256];

    // ---- load A tile with fused transforms, split to bf16 hi/lo ----
#pragma unroll
    for (int j = 0; j < 16; j++) {
        int v4 = tid + j * 256;
        int r = v4 >> 5, c4 = v4 & 31;
        int row = row0 + r;
        float4 a = make_float4(0.f, 0.f, 0.f, 0.f);
        if (row < N_NODES) {
            a = *(const float4*)(A + (size_t)row * lda + c4 * 4);
            if (MODE == 1) {
                float4 sc = ((const float4*)aux0)[c4];
                float4 sh = ((const float4*)aux1)[c4];
                a.x = fmaf(a.x, sc.x, sh.x); a.y = fmaf(a.y, sc.y, sh.y);
                a.z = fmaf(a.z, sc.z, sh.z); a.w = fmaf(a.w, sc.w, sh.w);
            } else if (MODE == 2) {
                float4 bb = ((const float4*)aux0)[c4];
                a.x = fmaxf(a.x + bb.x, 0.f); a.y = fmaxf(a.y + bb.y, 0.f);
                a.z = fmaxf(a.z + bb.z, 0.f); a.w = fmaxf(a.w + bb.w, 0.f);
            }
        }
        __nv_bfloat16 h0 = __float2bfloat16(a.x), h1 = __float2bfloat16(a.y);
        __nv_bfloat16 h2 = __float2bfloat16(a.z), h3 = __float2bfloat16(a.w);
        __nv_bfloat16 l0 = __float2bfloat16(a.x - __bfloat162float(h0));
        __nv_bfloat16 l1 = __float2bfloat16(a.y - __bfloat162float(h1));
        __nv_bfloat16 l2 = __float2bfloat16(a.z - __bfloat162float(h2));
        __nv_bfloat16 l3 = __float2bfloat16(a.w - __bfloat162float(h3));
        uint2 uh = make_uint2(pack_bf2(h0, h1), pack_bf2(h2, h3));
        uint2 ul = make_uint2(pack_bf2(l0, l1), pack_bf2(l2, l3));
        *(uint2*)&sAh[r * KP + c4 * 4] = uh;
        *(uint2*)&sAl[r * KP + c4 * 4] = ul;
    }
    __syncthreads();

    // ---- mma mainloop: warp = 16 rows x full 128 cols ----
    const int lr = lane >> 2, lq = lane & 3;
    const int m0 = wid * 16;
    float acc[16][4];
#pragma unroll
    for (int nb = 0; nb < 16; nb++)
#pragma unroll
        for (int i = 0; i < 4; i++) acc[nb][i] = 0.f;

    const __nv_bfloat16* pAh = sAh + (m0 + lr) * KP;
    const __nv_bfloat16* pAl = sAl + (m0 + lr) * KP;
#pragma unroll
    for (int ks = 0; ks < 8; ks++) {
        const int kc = ks * 16 + 2 * lq;
        uint32_t ah0 = *(const uint32_t*)(pAh + kc);
        uint32_t ah1 = *(const uint32_t*)(pAh + 8 * KP + kc);
        uint32_t ah2 = *(const uint32_t*)(pAh + kc + 8);
        uint32_t ah3 = *(const uint32_t*)(pAh + 8 * KP + kc + 8);
        uint32_t al0 = *(const uint32_t*)(pAl + kc);
        uint32_t al1 = *(const uint32_t*)(pAl + 8 * KP + kc);
        uint32_t al2 = *(const uint32_t*)(pAl + kc + 8);
        uint32_t al3 = *(const uint32_t*)(pAl + 8 * KP + kc + 8);
#pragma unroll
        for (int nb = 0; nb < 16; nb++) {
            const __nv_bfloat16* pB = sBh + (nb * 8 + lr) * KP + kc;
            uint32_t bh0 = *(const uint32_t*)pB;
            uint32_t bh1 = *(const uint32_t*)(pB + 8);
            mma_bf16(acc[nb], ah0, ah1, ah2, ah3, bh0, bh1);
            mma_bf16(acc[nb], al0, al1, al2, al3, bh0, bh1);
            const __nv_bfloat16* pBl = sBl + (nb * 8 + lr) * KP + kc;
            uint32_t bl0 = *(const uint32_t*)pBl;
            uint32_t bl1 = *(const uint32_t*)(pBl + 8);
            mma_bf16(acc[nb], ah0, ah1, ah2, ah3, bl0, bl1);
        }
    }

    // ---- epilogue ----
    const int r0 = row0 + m0 + lr;
    const int r1 = r0 + 8;
    int zi0 = 0, zi1 = 0;
    if (MODE == 0) {
        if (r0 < N_NODES) zi0 = z[r0];
        if (r1 < N_NODES) zi1 = z[r1];
    }
#pragma unroll
    for (int nb = 0; nb < 16; nb++) {
        const int c = nb * 8 + 2 * lq;
        float2 v0 = make_float2(acc[nb][0], acc[nb][1]);
        float2 v1 = make_float2(acc[nb][2], acc[nb][3]);
        if (MODE == 0) {
            if (r0 < N_NODES) {
                float2 e = *(const float2*)&Wfull[(size_t)zi0 * 128 + c];
                float2 f = *(const float2*)&Wfull[(size_t)(100 + zi0) * 128 + c];
                v0.x += e.x + f.x; v0.y += e.y + f.y;
            }
            if (r1 < N_NODES) {
                float2 e = *(const float2*)&Wfull[(size_t)zi1 * 128 + c];
                float2 f = *(const float2*)&Wfull[(size_t)(100 + zi1) * 128 + c];
                v1.x += e.x + f.x; v1.y += e.y + f.y;
            }
        }
        if (MODE == 2) {
            float2 bb = *(const float2*)&b2[c];
            v0.x = fmaxf(v0.x + bb.x, 0.f); v0.y = fmaxf(v0.y + bb.y, 0.f);
            v1.x = fmaxf(v1.x + bb.x, 0.f); v1.y = fmaxf(v1.y + bb.y, 0.f);
        }
        if (r0 < N_NODES) {
            *(float2*)&out0[(size_t)r0 * ld0 + c] = v0;
            if (MODE < 2) *(float2*)&out1[(size_t)r0 * 128 + c] = v0;
        }
        if (r1 < N_NODES) {
            *(float2*)&out0[(size_t)r1 * ld0 + c] = v1;
            if (MODE < 2) *(float2*)&out1[(size_t)r1 * 128 + c] = v1;
        }
    }
}

// ---------------- edge scatter: agg[dst] += y[src] (warp per edge) ----------------
__global__ void k_scatter(const int* __restrict__ src, const int* __restrict__ dst) {
    int e = blockIdx.x * 8 + (threadIdx.x >> 5);
    if (e >= N_EDGES) return;
    int lane = threadIdx.x & 31;
    int s = src[e];
    int d = dst[e];
    float4 v = *(const float4*)&g_y[(size_t)s * 128 + lane * 4];
    red_add_v4(&g_agg[(size_t)d * 128 + lane * 4], v);
}

// ---------------- BN stats over an xs slice ----------------
__global__ void k_bn_stats(const float* __restrict__ xs, int l) {
    __shared__ float ssum[128], ssq[128];
    int tid = threadIdx.x;
    if (tid < 128) { ssum[tid] = 0.f; ssq[tid] = 0.f; }
    __syncthreads();
    int c4 = tid & 31, rg = tid >> 5;
    float4 s = make_float4(0.f, 0.f, 0.f, 0.f);
    float4 q = make_float4(0.f, 0.f, 0.f, 0.f);
    for (int row = blockIdx.x * 8 + rg; row < N_NODES; row += gridDim.x * 8) {
        float4 v = *(const float4*)(xs + (size_t)row * XSD + c4 * 4);
        s.x += v.x; s.y += v.y; s.z += v.z; s.w += v.w;
        q.x += v.x * v.x; q.y += v.y * v.y; q.z += v.z * v.z; q.w += v.w * v.w;
    }
    atomicAdd(&ssum[c4 * 4 + 0], s.x); atomicAdd(&ssum[c4 * 4 + 1], s.y);
    atomicAdd(&ssum[c4 * 4 + 2], s.z); atomicAdd(&ssum[c4 * 4 + 3], s.w);
    atomicAdd(&ssq[c4 * 4 + 0], q.x);  atomicAdd(&ssq[c4 * 4 + 1], q.y);
    atomicAdd(&ssq[c4 * 4 + 2], q.z);  atomicAdd(&ssq[c4 * 4 + 3], q.w);
    __syncthreads();
    if (tid < 128) {
        atomicAdd(&g_sum[l * 128 + tid], ssum[tid]);
        atomicAdd(&g_sumsq[l * 128 + tid], ssq[tid]);
    }
}

__global__ void k_bn_final(const float* __restrict__ gam, const float* __restrict__ bet, int l) {
    int c = threadIdx.x;
    const float invN = 1.0f / (float)N_NODES;
    float mu = g_sum[l * 128 + c] * invN;
    float var = g_sumsq[l * 128 + c] * invN - mu * mu;
    float s = gam[c] * rsqrtf(fmaxf(var, 0.f) + 1e-5f);
    g_scale[l * 128 + c] = s;
    g_shift[l * 128 + c] = bet[c] - mu * s;
}

// ---------------- pooling ----------------
__global__ void k_zero_pool() {
    int idx = blockIdx.x * blockDim.x + threadIdx.x;
    if (idx < GG * XSD / 4) ((float4*)g_pooled)[idx] = make_float4(0.f, 0.f, 0.f, 0.f);
    if (idx < GG) g_counts[idx] = 0;
}

__global__ void k_counts(const int* __restrict__ batch) {
    __shared__ int h[GG];
    for (int i = threadIdx.x; i < GG; i += blockDim.x) h[i] = 0;
    __syncthreads();
    for (int i = blockIdx.x * blockDim.x + threadIdx.x; i < N_NODES; i += gridDim.x * blockDim.x)
        atomicAdd(&h[batch[i]], 1);
    __syncthreads();
    for (int i = threadIdx.x; i < GG; i += blockDim.x)
        if (h[i]) atomicAdd(&g_counts[i], h[i]);
}

__global__ void k_pool(const int* __restrict__ batch) {
    int i = blockIdx.x * 8 + (threadIdx.x >> 5);
    if (i >= N_NODES) return;
    int lane = threadIdx.x & 31;
    int b = batch[i];
    const float4* xr = (const float4*)g_xs + (size_t)i * 96;
    float4* pr = (float4*)g_pooled + (size_t)b * 96;
#pragma unroll
    for (int j = 0; j < 3; j++) {
        float4 v = xr[lane + j * 32];
        red_add_v4((float*)(pr + lane + j * 32), v);
    }
}

// ---------------- final MLP (BN affine folded into pooled sums) ----------------
__global__ void __launch_bounds__(128) k_mlp(
    const float* __restrict__ Wl1, const float* __restrict__ bl1,
    const float* __restrict__ Wl2, const float* __restrict__ bl2,
    float* __restrict__ out)
{
    int g = blockIdx.x;
    int c = threadIdx.x;
    __shared__ float sp[XSD];
    __shared__ float red[128];
    float cnt = (float)g_counts[g];
    float inv = 1.0f / fmaxf(cnt, 1.0f);
    for (int k = c; k < XSD; k += 128)
        sp[k] = (g_pooled[(size_t)g * XSD + k] * g_scale[k] + cnt * g_shift[k]) * inv;
    __syncthreads();
    float acc = bl1[c];
    for (int k = 0; k < XSD; k++) acc += sp[k] * Wl1[(size_t)k * 128 + c];
    red[c] = fmaxf(acc, 0.f) * Wl2[c];
    __syncthreads();
    for (int s = 64; s > 0; s >>= 1) {
        if (c < s) red[c] += red[c + s];
        __syncthreads();
    }
    if (c == 0) out[g] = red[0] + bl2[0];
}

// ---------------- host ----------------
extern "C" void kernel_launch(void* const* d_in, const int* in_sizes, int n_in,
                              void* d_out, int out_size) {
    (void)in_sizes; (void)n_in; (void)out_size;
    const float* x     = (const float*)d_in[0];
    const int*   z     = (const int*)d_in[1];
    const int*   ei    = (const int*)d_in[2];
    const int*   batch = (const int*)d_in[3];
    const float *W1[3], *b1[3], *W2[3], *b2[3], *gam[3], *bet[3];
    for (int l = 0; l < 3; l++) {
        W1[l]  = (const float*)d_in[4 + 6 * l];
        b1[l]  = (const float*)d_in[5 + 6 * l];
        W2[l]  = (const float*)d_in[6 + 6 * l];
        b2[l]  = (const float*)d_in[7 + 6 * l];
        gam[l] = (const float*)d_in[8 + 6 * l];
        bet[l] = (const float*)d_in[9 + 6 * l];
    }
    const float* Wl1 = (const float*)d_in[22];
    const float* bl1 = (const float*)d_in[23];
    const float* Wl2 = (const float*)d_in[24];
    const float* bl2 = (const float*)d_in[25];
    const int* src = ei;
    const int* dst = ei + N_EDGES;

    void *yp, *aggp, *xsp, *wp, *scp, *shp;
    cudaGetSymbolAddress(&yp, g_y);
    cudaGetSymbolAddress(&aggp, g_agg);
    cudaGetSymbolAddress(&xsp, g_xs);
    cudaGetSymbolAddress(&wp, g_wimg);
    cudaGetSymbolAddress(&scp, g_scale);
    cudaGetSymbolAddress(&shp, g_shift);
    float* yb   = (float*)yp;
    float* aggb = (float*)aggp;
    float* xsb  = (float*)xsp;
    uint4* wimg = (uint4*)wp;
    float* scb  = (float*)scp;
    float* shb  = (float*)shp;

    cudaFuncSetAttribute(k_mma<0>, cudaFuncAttributeMaxDynamicSharedMemorySize, SMEM_BYTES);
    cudaFuncSetAttribute(k_mma<1>, cudaFuncAttributeMaxDynamicSharedMemorySize, SMEM_BYTES);
    cudaFuncSetAttribute(k_mma<2>, cudaFuncAttributeMaxDynamicSharedMemorySize, SMEM_BYTES);

    const int GR_E = (N_EDGES + 7) / 8;      // 200000
    const int GR_P = (N_NODES + 7) / 8;      // 12500

    // weight images: layer0 gemm1 uses W1_0 rows 200..327 (x-part)
    k_prep<<<7, 256>>>(W1[0] + 200 * 128, W2[0], W1[1], W2[1], W1[2], W2[2]);

    for (int l = 0; l < 3; l++) {
        if (l == 0) {
            k_mma<0><<<NB, 256, SMEM_BYTES>>>(x, 128, wimg, nullptr, nullptr,
                                              z, W1[0], nullptr, yb, 128, aggb);
        } else {
            k_mma<1><<<NB, 256, SMEM_BYTES>>>(xsb + (size_t)(l - 1) * 128, XSD,
                                              wimg + (size_t)(2 * l) * 4352,
                                              scb + (l - 1) * 128, shb + (l - 1) * 128,
                                              nullptr, nullptr, nullptr, yb, 128, aggb);
        }
        k_scatter<<<GR_E, 256>>>(src, dst);
        k_mma<2><<<NB, 256, SMEM_BYTES>>>(aggb, 128, wimg + (size_t)(2 * l + 1) * 4352,
                                          b1[l], nullptr, nullptr, nullptr, b2[l],
                                          xsb + (size_t)l * 128, XSD, nullptr);
        k_bn_stats<<<256, 256>>>(xsb + (size_t)l * 128, l);
        k_bn_final<<<1, 128>>>(gam[l], bet[l], l);
    }

    k_zero_pool<<<192, 256>>>();
    k_counts<<<128, 256>>>(batch);
    k_pool<<<GR_P, 256>>>(batch);
    k_mlp<<<GG, 128>>>(Wl1, bl1, Wl2, bl2, (float*)d_out);
}

// round 5
// speedup vs baseline: 1.7927x; 1.4285x over previous
#include <cuda_runtime.h>
#include <cuda_bf16.h>
#include <cstdint>

#define N_NODES 100000
#define N_EDGES 1600000
#define HID 128
#define GG 512
#define XSD 384
#define NB 782                          // ceil(100000/128)
#define KP 136                          // smem pitch in bf16 elems
#define AIMG (128 * KP)                 // elems per tile image
#define SMEM_BYTES (4 * AIMG * 2 + 1024)
#define NBLK1 98                        // ceil(100000/1024)

// ---------------- scratch (static device globals; no allocation) ----------------
__device__ float g_y[N_NODES * HID];      // pre-aggregation features (gather source)
__device__ float g_agg[N_NODES * HID];    // self + edge aggregation
__device__ float g_xs[N_NODES * XSD];     // per-layer raw (pre-BN-affine) outputs
__device__ uint4 g_wimg[6 * 4352];        // 6 weights x (hi+lo) bf16 images [n][k] pitch KP
__device__ float g_pooled[GG * XSD];
__device__ float g_sum[3 * HID];
__device__ float g_sumsq[3 * HID];
__device__ float g_scale[3 * HID];
__device__ float g_shift[3 * HID];
__device__ int   g_counts[GG];
// CSR scratch
__device__ int g_deg[NBLK1 * 1024];
__device__ int g_incl[NBLK1 * 1024];
__device__ int g_start[N_NODES];
__device__ int g_cur[N_NODES];
__device__ int g_ssrc[N_EDGES];
__device__ int g_bsum[128];

// ---------------- helpers ----------------
__device__ __forceinline__ void red_add_v4(float* p, float4 v) {
    asm volatile("red.global.add.v4.f32 [%0], {%1, %2, %3, %4};"
                 :: "l"(p), "f"(v.x), "f"(v.y), "f"(v.z), "f"(v.w) : "memory");
}
__device__ __forceinline__ void mma_bf16(float* c, uint32_t a0, uint32_t a1, uint32_t a2,
                                         uint32_t a3, uint32_t b0, uint32_t b1) {
    asm volatile(
        "mma.sync.aligned.m16n8k16.row.col.f32.bf16.bf16.f32 "
        "{%0,%1,%2,%3}, {%4,%5,%6,%7}, {%8,%9}, {%0,%1,%2,%3};"
        : "+f"(c[0]), "+f"(c[1]), "+f"(c[2]), "+f"(c[3])
        : "r"(a0), "r"(a1), "r"(a2), "r"(a3), "r"(b0), "r"(b1));
}
__device__ __forceinline__ uint32_t pack_bf2(__nv_bfloat16 lo, __nv_bfloat16 hi) {
    return (uint32_t)__bfloat16_as_ushort(lo) | ((uint32_t)__bfloat16_as_ushort(hi) << 16);
}

// ---------------- weight prep + stat zero ----------------
__global__ void k_prep(const float* __restrict__ w0, const float* __restrict__ w1,
                       const float* __restrict__ w2, const float* __restrict__ w3,
                       const float* __restrict__ w4, const float* __restrict__ w5) {
    int bb = blockIdx.x;
    if (bb < 6) {
        const float* W = bb == 0 ? w0 : bb == 1 ? w1 : bb == 2 ? w2 : bb == 3 ? w3 : bb == 4 ? w4 : w5;
        __nv_bfloat16* img = ((__nv_bfloat16*)g_wimg) + (size_t)bb * 2 * AIMG;
        for (int idx = threadIdx.x; idx < 16384; idx += 256) {
            int k = idx >> 7, n = idx & 127;
            float w = W[idx];
            __nv_bfloat16 h = __float2bfloat16(w);
            __nv_bfloat16 l = __float2bfloat16(w - __bfloat162float(h));
            img[n * KP + k] = h;
            img[AIMG + n * KP + k] = l;
        }
    } else {
        for (int i = threadIdx.x; i < 3 * HID; i += 256) { g_sum[i] = 0.f; g_sumsq[i] = 0.f; }
    }
}

// ---------------- CSR build (once per launch) ----------------
__global__ void k_zero_deg() {
    int i = blockIdx.x * blockDim.x + threadIdx.x;
    if (i < NBLK1 * 1024) g_deg[i] = 0;
}
__global__ void k_hist(const int* __restrict__ dst) {
    int e = blockIdx.x * blockDim.x + threadIdx.x;
    if (e < N_EDGES) atomicAdd(&g_deg[dst[e]], 1);
}
__global__ void __launch_bounds__(256) k_scan1() {
    __shared__ int s[256];
    int b = blockIdx.x, t = threadIdx.x;
    int base = b * 1024 + t * 4;
    int v0 = g_deg[base], v1 = g_deg[base + 1], v2 = g_deg[base + 2], v3 = g_deg[base + 3];
    int s0 = v0, s1 = s0 + v1, s2 = s1 + v2, s3 = s2 + v3;
    s[t] = s3;
    __syncthreads();
    for (int off = 1; off < 256; off <<= 1) {
        int x = (t >= off) ? s[t - off] : 0;
        __syncthreads();
        if (t >= off) s[t] += x;
        __syncthreads();
    }
    int prev = (t > 0) ? s[t - 1] : 0;
    g_incl[base] = prev + s0; g_incl[base + 1] = prev + s1;
    g_incl[base + 2] = prev + s2; g_incl[base + 3] = prev + s3;
    if (t == 255) g_bsum[b] = s[255];
}
__global__ void __launch_bounds__(128) k_scan2() {
    __shared__ int s[128];
    int t = threadIdx.x;
    s[t] = (t < NBLK1) ? g_bsum[t] : 0;
    __syncthreads();
    for (int off = 1; off < 128; off <<= 1) {
        int x = (t >= off) ? s[t - off] : 0;
        __syncthreads();
        if (t >= off) s[t] += x;
        __syncthreads();
    }
    if (t < NBLK1) g_bsum[t] = (t > 0) ? s[t - 1] : 0;   // exclusive block offsets
}
__global__ void k_scan3() {
    int i = blockIdx.x * blockDim.x + threadIdx.x;
    if (i >= N_NODES) return;
    int st = g_incl[i] - g_deg[i] + g_bsum[i >> 10];
    g_start[i] = st;
    g_cur[i] = st;
}
__global__ void k_permute(const int* __restrict__ src, const int* __restrict__ dst) {
    int e = blockIdx.x * blockDim.x + threadIdx.x;
    if (e >= N_EDGES) return;
    int p = atomicAdd(&g_cur[dst[e]], 1);
    g_ssrc[p] = src[e];
}

// ---------------- gather: agg[d] = y[d] + sum_{e: dst=d} y[src[e]] ----------------
__global__ void __launch_bounds__(256) k_gather() {
    int d = blockIdx.x * 8 + (threadIdx.x >> 5);
    if (d >= N_NODES) return;
    int lane = threadIdx.x & 31;
    const float4* Y = (const float4*)g_y;
    float4 acc = Y[(size_t)d * 32 + lane];          // self term
    int s = g_start[d], n = g_deg[d];
    int e = s, end = s + n;
    for (; e + 4 <= end; e += 4) {
        int i0 = g_ssrc[e], i1 = g_ssrc[e + 1], i2 = g_ssrc[e + 2], i3 = g_ssrc[e + 3];
        float4 v0 = Y[(size_t)i0 * 32 + lane];
        float4 v1 = Y[(size_t)i1 * 32 + lane];
        float4 v2 = Y[(size_t)i2 * 32 + lane];
        float4 v3 = Y[(size_t)i3 * 32 + lane];
        acc.x += v0.x + v1.x + v2.x + v3.x;
        acc.y += v0.y + v1.y + v2.y + v3.y;
        acc.z += v0.z + v1.z + v2.z + v3.z;
        acc.w += v0.w + v1.w + v2.w + v3.w;
    }
    for (; e < end; e++) {
        int i0 = g_ssrc[e];
        float4 v0 = Y[(size_t)i0 * 32 + lane];
        acc.x += v0.x; acc.y += v0.y; acc.z += v0.z; acc.w += v0.w;
    }
    ((float4*)g_agg)[(size_t)d * 32 + lane] = acc;
}

// ---------------- fused bf16x3 GEMM, 512 threads, warp tile 32x32 ----------------
// MODE 0: A = x,                   epi: v = D + W1[z] + W1[100+z]; write y
// MODE 1: A = xs_prev*scale+shift, epi: v = D;                     write y
// MODE 2: A = relu(A + b1),        epi: v = relu(D + b2);          write xs slice + BN stats
template <int MODE>
__global__ void __launch_bounds__(512, 1) k_mma(
    const float* __restrict__ A, int lda,
    const uint4* __restrict__ Wimg,
    const float* __restrict__ aux0,   // MODE1: scale  MODE2: b1
    const float* __restrict__ aux1,   // MODE1: shift
    const int* __restrict__ z,        // MODE0
    const float* __restrict__ Wfull,  // MODE0: full W1_0
    const float* __restrict__ b2,     // MODE2
    float* __restrict__ out0, int ld0,
    int layer)
{
    extern __shared__ char smem[];
    __nv_bfloat16* sAh = (__nv_bfloat16*)smem;
    __nv_bfloat16* sAl = sAh + AIMG;
    __nv_bfloat16* sBh = sAl + AIMG;
    __nv_bfloat16* sBl = sBh + AIMG;
    float* s_sum = (float*)(smem + 4 * AIMG * 2);
    float* s_sq  = s_sum + 128;
    const int tid = threadIdx.x;
    const int wid = tid >> 5, lane = tid & 31;
    const int row0 = blockIdx.x * 128;

    if (MODE == 2 && tid < 256) { s_sum[tid & 127] = 0.f; s_sq[tid & 127] = 0.f; }

    // ---- copy pre-split B images (hi+lo = 4352 uint4) ----
    uint4* sB4 = (uint4*)sBh;
#pragma unroll
    for (int j = 0; j < 9; j++) {
        int idx = tid + j * 512;
        if (idx < 4352) sB4[idx] = Wimg[idx];
    }

    // ---- load A tile with fused transforms, split bf16 hi/lo ----
#pragma unroll
    for (int j = 0; j < 8; j++) {
        int v4 = tid + j * 512;
        int r = v4 >> 5, c4 = v4 & 31;
        int row = row0 + r;
        float4 a = make_float4(0.f, 0.f, 0.f, 0.f);
        if (row < N_NODES) {
            a = *(const float4*)(A + (size_t)row * lda + c4 * 4);
            if (MODE == 1) {
                float4 sc = ((const float4*)aux0)[c4];
                float4 sh = ((const float4*)aux1)[c4];
                a.x = fmaf(a.x, sc.x, sh.x); a.y = fmaf(a.y, sc.y, sh.y);
                a.z = fmaf(a.z, sc.z, sh.z); a.w = fmaf(a.w, sc.w, sh.w);
            } else if (MODE == 2) {
                float4 bb = ((const float4*)aux0)[c4];
                a.x = fmaxf(a.x + bb.x, 0.f); a.y = fmaxf(a.y + bb.y, 0.f);
                a.z = fmaxf(a.z + bb.z, 0.f); a.w = fmaxf(a.w + bb.w, 0.f);
            }
        }
        __nv_bfloat16 h0 = __float2bfloat16(a.x), h1 = __float2bfloat16(a.y);
        __nv_bfloat16 h2 = __float2bfloat16(a.z), h3 = __float2bfloat16(a.w);
        __nv_bfloat16 l0 = __float2bfloat16(a.x - __bfloat162float(h0));
        __nv_bfloat16 l1 = __float2bfloat16(a.y - __bfloat162float(h1));
        __nv_bfloat16 l2 = __float2bfloat16(a.z - __bfloat162float(h2));
        __nv_bfloat16 l3 = __float2bfloat16(a.w - __bfloat162float(h3));
        *(uint2*)&sAh[r * KP + c4 * 4] = make_uint2(pack_bf2(h0, h1), pack_bf2(h2, h3));
        *(uint2*)&sAl[r * KP + c4 * 4] = make_uint2(pack_bf2(l0, l1), pack_bf2(l2, l3));
    }
    __syncthreads();

    // ---- mainloop: warp (wm, wn) covers rows wm*32..+32, cols wn*32..+32 ----
    const int wm = wid & 3, wn = wid >> 2;
    const int lr = lane >> 2, lq = lane & 3;
    float acc[2][4][4];
#pragma unroll
    for (int mt = 0; mt < 2; mt++)
#pragma unroll
        for (int nb = 0; nb < 4; nb++)
#pragma unroll
            for (int i = 0; i < 4; i++) acc[mt][nb][i] = 0.f;

#pragma unroll
    for (int ks = 0; ks < 8; ks++) {
        const int kc = ks * 16 + 2 * lq;
        uint32_t ah[2][4], al[2][4];
#pragma unroll
        for (int mt = 0; mt < 2; mt++) {
            const __nv_bfloat16* p = sAh + (wm * 32 + mt * 16 + lr) * KP;
            const __nv_bfloat16* q = sAl + (wm * 32 + mt * 16 + lr) * KP;
            ah[mt][0] = *(const uint32_t*)(p + kc);
            ah[mt][1] = *(const uint32_t*)(p + 8 * KP + kc);
            ah[mt][2] = *(const uint32_t*)(p + kc + 8);
            ah[mt][3] = *(const uint32_t*)(p + 8 * KP + kc + 8);
            al[mt][0] = *(const uint32_t*)(q + kc);
            al[mt][1] = *(const uint32_t*)(q + 8 * KP + kc);
            al[mt][2] = *(const uint32_t*)(q + kc + 8);
            al[mt][3] = *(const uint32_t*)(q + 8 * KP + kc + 8);
        }
#pragma unroll
        for (int nb = 0; nb < 4; nb++) {
            const __nv_bfloat16* pB = sBh + (wn * 32 + nb * 8 + lr) * KP + kc;
            const __nv_bfloat16* pL = sBl + (wn * 32 + nb * 8 + lr) * KP + kc;
            uint32_t bh0 = *(const uint32_t*)pB;
            uint32_t bh1 = *(const uint32_t*)(pB + 8);
            uint32_t bl0 = *(const uint32_t*)pL;
            uint32_t bl1 = *(const uint32_t*)(pL + 8);
#pragma unroll
            for (int mt = 0; mt < 2; mt++) {
                mma_bf16(acc[mt][nb], ah[mt][0], ah[mt][1], ah[mt][2], ah[mt][3], bh0, bh1);
                mma_bf16(acc[mt][nb], al[mt][0], al[mt][1], al[mt][2], al[mt][3], bh0, bh1);
                mma_bf16(acc[mt][nb], ah[mt][0], ah[mt][1], ah[mt][2], ah[mt][3], bl0, bl1);
            }
        }
    }

    // ---- epilogue ----
    float ps0[4], ps1[4], pq0[4], pq1[4];
    if (MODE == 2) {
#pragma unroll
        for (int nb = 0; nb < 4; nb++) { ps0[nb] = 0.f; ps1[nb] = 0.f; pq0[nb] = 0.f; pq1[nb] = 0.f; }
    }
#pragma unroll
    for (int mt = 0; mt < 2; mt++) {
        const int r0 = row0 + wm * 32 + mt * 16 + lr;
        const int r1 = r0 + 8;
        int zi0 = 0, zi1 = 0;
        if (MODE == 0) {
            if (r0 < N_NODES) zi0 = z[r0];
            if (r1 < N_NODES) zi1 = z[r1];
        }
#pragma unroll
        for (int nb = 0; nb < 4; nb++) {
            const int c = wn * 32 + nb * 8 + 2 * lq;
            float2 v0 = make_float2(acc[mt][nb][0], acc[mt][nb][1]);
            float2 v1 = make_float2(acc[mt][nb][2], acc[mt][nb][3]);
            if (MODE == 0) {
                if (r0 < N_NODES) {
                    float2 e = *(const float2*)&Wfull[(size_t)zi0 * 128 + c];
                    float2 f = *(const float2*)&Wfull[(size_t)(100 + zi0) * 128 + c];
                    v0.x += e.x + f.x; v0.y += e.y + f.y;
                }
                if (r1 < N_NODES) {
                    float2 e = *(const float2*)&Wfull[(size_t)zi1 * 128 + c];
                    float2 f = *(const float2*)&Wfull[(size_t)(100 + zi1) * 128 + c];
                    v1.x += e.x + f.x; v1.y += e.y + f.y;
                }
            }
            if (MODE == 2) {
                float2 bb = *(const float2*)&b2[c];
                v0.x = fmaxf(v0.x + bb.x, 0.f); v0.y = fmaxf(v0.y + bb.y, 0.f);
                v1.x = fmaxf(v1.x + bb.x, 0.f); v1.y = fmaxf(v1.y + bb.y, 0.f);
            }
            if (r0 < N_NODES) {
                *(float2*)&out0[(size_t)r0 * ld0 + c] = v0;
                if (MODE == 2) { ps0[nb] += v0.x; ps1[nb] += v0.y; pq0[nb] += v0.x * v0.x; pq1[nb] += v0.y * v0.y; }
            }
            if (r1 < N_NODES) {
                *(float2*)&out0[(size_t)r1 * ld0 + c] = v1;
                if (MODE == 2) { ps0[nb] += v1.x; ps1[nb] += v1.y; pq0[nb] += v1.x * v1.x; pq1[nb] += v1.y * v1.y; }
            }
        }
    }
    if (MODE == 2) {
        __syncthreads();   // s_sum init visible (done pre-mainloop) & ordering
#pragma unroll
        for (int nb = 0; nb < 4; nb++) {
            const int c = wn * 32 + nb * 8 + 2 * lq;
            atomicAdd(&s_sum[c], ps0[nb]);
            atomicAdd(&s_sum[c + 1], ps1[nb]);
            atomicAdd(&s_sq[c], pq0[nb]);
            atomicAdd(&s_sq[c + 1], pq1[nb]);
        }
        __syncthreads();
        if (tid < 128) {
            atomicAdd(&g_sum[layer * 128 + tid], s_sum[tid]);
            atomicAdd(&g_sumsq[layer * 128 + tid], s_sq[tid]);
        }
    }
}

__global__ void k_bn_final(const float* __restrict__ gam, const float* __restrict__ bet, int l) {
    int c = threadIdx.x;
    const float invN = 1.0f / (float)N_NODES;
    float mu = g_sum[l * 128 + c] * invN;
    float var = g_sumsq[l * 128 + c] * invN - mu * mu;
    float s = gam[c] * rsqrtf(fmaxf(var, 0.f) + 1e-5f);
    g_scale[l * 128 + c] = s;
    g_shift[l * 128 + c] = bet[c] - mu * s;
}

// ---------------- pooling ----------------
__global__ void k_zero_pool() {
    int idx = blockIdx.x * blockDim.x + threadIdx.x;
    if (idx < GG * XSD / 4) ((float4*)g_pooled)[idx] = make_float4(0.f, 0.f, 0.f, 0.f);
    if (idx < GG) g_counts[idx] = 0;
}
__global__ void k_counts(const int* __restrict__ batch) {
    __shared__ int h[GG];
    for (int i = threadIdx.x; i < GG; i += blockDim.x) h[i] = 0;
    __syncthreads();
    for (int i = blockIdx.x * blockDim.x + threadIdx.x; i < N_NODES; i += gridDim.x * blockDim.x)
        atomicAdd(&h[batch[i]], 1);
    __syncthreads();
    for (int i = threadIdx.x; i < GG; i += blockDim.x)
        if (h[i]) atomicAdd(&g_counts[i], h[i]);
}
__global__ void k_pool(const int* __restrict__ batch) {
    int i = blockIdx.x * 8 + (threadIdx.x >> 5);
    if (i >= N_NODES) return;
    int lane = threadIdx.x & 31;
    int b = batch[i];
    const float4* xr = (const float4*)g_xs + (size_t)i * 96;
    float4* pr = (float4*)g_pooled + (size_t)b * 96;
#pragma unroll
    for (int j = 0; j < 3; j++) {
        float4 v = xr[lane + j * 32];
        red_add_v4((float*)(pr + lane + j * 32), v);
    }
}

// ---------------- final MLP (BN affine folded into pooled sums) ----------------
__global__ void __launch_bounds__(128) k_mlp(
    const float* __restrict__ Wl1, const float* __restrict__ bl1,
    const float* __restrict__ Wl2, const float* __restrict__ bl2,
    float* __restrict__ out)
{
    int g = blockIdx.x;
    int c = threadIdx.x;
    __shared__ float sp[XSD];
    __shared__ float red[128];
    float cnt = (float)g_counts[g];
    float inv = 1.0f / fmaxf(cnt, 1.0f);
    for (int k = c; k < XSD; k += 128)
        sp[k] = (g_pooled[(size_t)g * XSD + k] * g_scale[k] + cnt * g_shift[k]) * inv;
    __syncthreads();
    float acc = bl1[c];
    for (int k = 0; k < XSD; k++) acc += sp[k] * Wl1[(size_t)k * 128 + c];
    red[c] = fmaxf(acc, 0.f) * Wl2[c];
    __syncthreads();
    for (int s = 64; s > 0; s >>= 1) {
        if (c < s) red[c] += red[c + s];
        __syncthreads();
    }
    if (c == 0) out[g] = red[0] + bl2[0];
}

// ---------------- host ----------------
extern "C" void kernel_launch(void* const* d_in, const int* in_sizes, int n_in,
                              void* d_out, int out_size) {
    (void)in_sizes; (void)n_in; (void)out_size;
    const float* x     = (const float*)d_in[0];
    const int*   z     = (const int*)d_in[1];
    const int*   ei    = (const int*)d_in[2];
    const int*   batch = (const int*)d_in[3];
    const float *W1[3], *b1[3], *W2[3], *b2[3], *gam[3], *bet[3];
    for (int l = 0; l < 3; l++) {
        W1[l]  = (const float*)d_in[4 + 6 * l];
        b1[l]  = (const float*)d_in[5 + 6 * l];
        W2[l]  = (const float*)d_in[6 + 6 * l];
        b2[l]  = (const float*)d_in[7 + 6 * l];
        gam[l] = (const float*)d_in[8 + 6 * l];
        bet[l] = (const float*)d_in[9 + 6 * l];
    }
    const float* Wl1 = (const float*)d_in[22];
    const float* bl1 = (const float*)d_in[23];
    const float* Wl2 = (const float*)d_in[24];
    const float* bl2 = (const float*)d_in[25];
    const int* src = ei;
    const int* dst = ei + N_EDGES;

    void *yp, *aggp, *xsp, *wp, *scp, *shp;
    cudaGetSymbolAddress(&yp, g_y);
    cudaGetSymbolAddress(&aggp, g_agg);
    cudaGetSymbolAddress(&xsp, g_xs);
    cudaGetSymbolAddress(&wp, g_wimg);
    cudaGetSymbolAddress(&scp, g_scale);
    cudaGetSymbolAddress(&shp, g_shift);
    float* yb   = (float*)yp;
    float* aggb = (float*)aggp;
    float* xsb  = (float*)xsp;
    uint4* wimg = (uint4*)wp;
    float* scb  = (float*)scp;
    float* shb  = (float*)shp;

    cudaFuncSetAttribute(k_mma<0>, cudaFuncAttributeMaxDynamicSharedMemorySize, SMEM_BYTES);
    cudaFuncSetAttribute(k_mma<1>, cudaFuncAttributeMaxDynamicSharedMemorySize, SMEM_BYTES);
    cudaFuncSetAttribute(k_mma<2>, cudaFuncAttributeMaxDynamicSharedMemorySize, SMEM_BYTES);

    // weight prep + CSR build (once; reused by all 3 layers)
    k_prep<<<7, 256>>>(W1[0] + 200 * 128, W2[0], W1[1], W2[1], W1[2], W2[2]);
    k_zero_deg<<<(NBLK1 * 1024 + 255) / 256, 256>>>();
    k_hist<<<(N_EDGES + 255) / 256, 256>>>(dst);
    k_scan1<<<NBLK1, 256>>>();
    k_scan2<<<1, 128>>>();
    k_scan3<<<(N_NODES + 255) / 256, 256>>>();
    k_permute<<<(N_EDGES + 255) / 256, 256>>>(src, dst);

    for (int l = 0; l < 3; l++) {
        if (l == 0) {
            k_mma<0><<<NB, 512, SMEM_BYTES>>>(x, 128, wimg, nullptr, nullptr,
                                              z, W1[0], nullptr, yb, 128, 0);
        } else {
            k_mma<1><<<NB, 512, SMEM_BYTES>>>(xsb + (size_t)(l - 1) * 128, XSD,
                                              wimg + (size_t)(2 * l) * 4352,
                                              scb + (l - 1) * 128, shb + (l - 1) * 128,
                                              nullptr, nullptr, nullptr, yb, 128, l);
        }
        k_gather<<<(N_NODES + 7) / 8, 256>>>();
        k_mma<2><<<NB, 512, SMEM_BYTES>>>(aggb, 128, wimg + (size_t)(2 * l + 1) * 4352,
                                          b1[l], nullptr, nullptr, nullptr, b2[l],
                                          xsb + (size_t)l * 128, XSD, l);
        k_bn_final<<<1, 128>>>(gam[l], bet[l], l);
    }

    k_zero_pool<<<192, 256>>>();
    k_counts<<<128, 256>>>(batch);
    k_pool<<<(N_NODES + 7) / 8, 256>>>(batch);
    k_mlp<<<GG, 128>>>(Wl1, bl1, Wl2, bl2, (float*)d_out);
}